// round 1
// baseline (speedup 1.0000x reference)
#include <cuda_runtime.h>
#include <math.h>

// ---------------- problem constants ----------------
namespace {
constexpr int D_   = 550;
constexpr int F_   = 275;
constexpr int B_   = 4096;   // N*T = 8*512
constexpr int H_   = 128;
constexpr int OUT_ = 6325;   // F_*(3*8-1)
}

// ---------------- scratch (device globals; no allocs allowed) ----------------
__device__ float g_z [B_*D_];
__device__ float g_zn[B_*D_];
__device__ float g_Ap[D_*D_];
__device__ float g_id[B_*F_];
__device__ float g_t [B_*H_];
__device__ float g_r [B_*H_];
__device__ float g_lq[B_];
__device__ float g_slog[3];

// ---------------- helpers ----------------
__device__ __forceinline__ float softplusf(float x) {
    return (x > 20.f) ? x : log1pf(__expf(x));
}

__device__ __forceinline__ float block_reduce_sum(float v) {
    __shared__ float sred[32];
    int tid = threadIdx.x;
    #pragma unroll
    for (int o = 16; o > 0; o >>= 1) v += __shfl_down_sync(0xffffffffu, v, o);
    if ((tid & 31) == 0) sred[tid >> 5] = v;
    __syncthreads();
    if (tid < 32) {
        int nw = (blockDim.x + 31) >> 5;
        v = (tid < nw) ? sred[tid] : 0.f;
        #pragma unroll
        for (int o = 16; o > 0; o >>= 1) v += __shfl_down_sync(0xffffffffu, v, o);
    }
    return v;  // valid in thread 0
}

// Inverse monotonic RQS with linear tails (nflows math). All register-resident.
__device__ __forceinline__ void rqs_inv(float x, const float* uw, const float* uh,
                                        const float* ud7, float& out, float& ld)
{
    const float TB = 3.f;
    bool inside = (x >= -TB) && (x <= TB);
    float xi = fminf(fmaxf(x, -TB), TB);

    float cw[9], ch[9], dd[9];
    // width knots
    {
        float m = uw[0];
        #pragma unroll
        for (int k = 1; k < 8; k++) m = fmaxf(m, uw[k]);
        float e[8]; float s = 0.f;
        #pragma unroll
        for (int k = 0; k < 8; k++) { e[k] = __expf(uw[k] - m); s += e[k]; }
        float inv = 1.f / s;
        float cum = 0.f;
        cw[0] = -TB;
        #pragma unroll
        for (int k = 0; k < 7; k++) { cum += 0.001f + 0.992f * e[k] * inv; cw[k+1] = 6.f * cum - 3.f; }
        cw[8] = TB;
    }
    // height knots
    {
        float m = uh[0];
        #pragma unroll
        for (int k = 1; k < 8; k++) m = fmaxf(m, uh[k]);
        float e[8]; float s = 0.f;
        #pragma unroll
        for (int k = 0; k < 8; k++) { e[k] = __expf(uh[k] - m); s += e[k]; }
        float inv = 1.f / s;
        float cum = 0.f;
        ch[0] = -TB;
        #pragma unroll
        for (int k = 0; k < 7; k++) { cum += 0.001f + 0.992f * e[k] * inv; ch[k+1] = 6.f * cum - 3.f; }
        ch[8] = TB;
    }
    // derivatives (pad with DCONST so end derivs = 1)
    const float DCONSTF = 0.53974175f;  // log(exp(0.999)-1)
    float dend = 0.001f + log1pf(__expf(DCONSTF));
    dd[0] = dend; dd[8] = dend;
    #pragma unroll
    for (int k = 0; k < 7; k++) dd[k+1] = 0.001f + softplusf(ud7[k]);

    // bin search on height knots
    int cnt = 0;
    #pragma unroll
    for (int k = 0; k < 9; k++) {
        float lo = ch[k] + (k == 8 ? 1e-6f : 0.f);
        cnt += (xi >= lo) ? 1 : 0;
    }
    int idx = cnt - 1; idx = idx < 0 ? 0 : (idx > 7 ? 7 : idx);

    float icw = 0.f, iw = 1.f, ich = 0.f, ih = 1.f, d0 = 1.f, d1 = 1.f;
    #pragma unroll
    for (int k = 0; k < 8; k++) {
        if (k == idx) {
            icw = cw[k]; iw = cw[k+1] - cw[k];
            ich = ch[k]; ih = ch[k+1] - ch[k];
            d0 = dd[k]; d1 = dd[k+1];
        }
    }

    float delta = ih / iw;
    float t  = xi - ich;
    float s2 = d0 + d1 - 2.f * delta;
    float aa = t * s2 + ih * (delta - d0);
    float bb = ih * d0 - t * s2;
    float cc = -delta * t;
    float disc = bb * bb - 4.f * aa * cc;
    float root = (2.f * cc) / (-bb - sqrtf(disc));
    float o = root * iw + icw;
    float tm = root * (1.f - root);
    float den = delta + s2 * tm;
    float omr = 1.f - root;
    float dnum = delta * delta * (d1 * root * root + 2.f * delta * tm + d0 * omr * omr);
    float l = 2.f * __logf(den) - __logf(dnum);

    out = inside ? o : x;
    ld  = inside ? l : 0.f;
}

// ---------------- kernels ----------------
__global__ void zero_kernel(float* p, int n) {
    int i = blockIdx.x * blockDim.x + threadIdx.x;
    if (i < n) p[i] = 0.f;
}

__global__ void sumlog_kernel(const float* __restrict__ lu_ud, float* __restrict__ out) {
    int i = blockIdx.x;  // layer
    float s = 0.f;
    for (int d = threadIdx.x; d < D_; d += blockDim.x)
        s += __logf(softplusf(lu_ud[i * D_ + d]) + 0.001f);
    s = block_reduce_sum(s);
    if (threadIdx.x == 0) out[i] = s;
}

// Ap[d, perm[k]] = (L@U)[d,k]
__global__ void build_A_kernel(const float* __restrict__ lower, const float* __restrict__ upper,
                               const float* __restrict__ ud, const int* __restrict__ perm,
                               float* __restrict__ Ap)
{
    int k = blockIdx.x * blockDim.x + threadIdx.x;
    int d = blockIdx.y;
    if (k >= D_) return;
    float diag_k = softplusf(ud[k]) + 0.001f;
    float s;
    if (d < k)       s = upper[d * D_ + k];
    else if (d == k) s = diag_k;
    else             s = 0.f;
    int mmax = min(d, k);
    for (int m = 0; m < mmax; m++)
        s += lower[d * D_ + m] * upper[m * D_ + k];
    if (k < d) s += lower[d * D_ + k] * diag_k;
    Ap[d * D_ + perm[k]] = s;
}

// Generic tiled SGEMM: C = act(A) @ B(+T) + bias (+ Cadd)
// A row-major [M x lda]; if BT: B row-major [N x ldb] (use B[n,k]); else [K x ldb].
template<int BM, int BN, int BK, int TM, int TN, bool BT, bool RELUA, bool ADDC>
__global__ void __launch_bounds__((BM/TM)*(BN/TN))
gemm_k(const float* __restrict__ A, const float* __restrict__ B,
       const float* __restrict__ bias, const float* __restrict__ Cadd,
       float* __restrict__ C, int M, int N, int K, int lda, int ldb, int ldc)
{
    constexpr int TX = BN / TN, TY = BM / TM, NT = TX * TY;
    __shared__ float As[BK][BM];
    __shared__ float Bs[BK][BN];
    int tid = threadIdx.x;
    int tx = tid % TX, ty = tid / TX;
    int m0 = blockIdx.y * BM, n0 = blockIdx.x * BN;
    float acc[TM][TN];
    #pragma unroll
    for (int i = 0; i < TM; i++)
        #pragma unroll
        for (int j = 0; j < TN; j++) acc[i][j] = 0.f;

    for (int k0 = 0; k0 < K; k0 += BK) {
        #pragma unroll
        for (int idx = tid; idx < BM * BK; idx += NT) {
            int r = idx / BK, c = idx % BK;
            int gm = m0 + r, gk = k0 + c;  // gm < M guaranteed (M % BM == 0)
            float v = (gk < K) ? A[gm * lda + gk] : 0.f;
            if (RELUA) v = fmaxf(v, 0.f);
            As[c][r] = v;
        }
        #pragma unroll
        for (int idx = tid; idx < BK * BN; idx += NT) {
            if (BT) {
                int r = idx / BK, c = idx % BK;  // r: n-local, c: k-local
                int gn = n0 + r, gk = k0 + c;
                Bs[c][r] = (gn < N && gk < K) ? B[gn * ldb + gk] : 0.f;
            } else {
                int r = idx / BN, c = idx % BN;  // r: k-local, c: n-local
                int gk = k0 + r, gn = n0 + c;
                Bs[r][c] = (gk < K && gn < N) ? B[gk * ldb + gn] : 0.f;
            }
        }
        __syncthreads();
        #pragma unroll
        for (int kk = 0; kk < BK; kk++) {
            float ra[TM], rb[TN];
            #pragma unroll
            for (int i = 0; i < TM; i++) ra[i] = As[kk][ty * TM + i];
            #pragma unroll
            for (int j = 0; j < TN; j++) rb[j] = Bs[kk][tx * TN + j];
            #pragma unroll
            for (int i = 0; i < TM; i++)
                #pragma unroll
                for (int j = 0; j < TN; j++)
                    acc[i][j] += ra[i] * rb[j];
        }
        __syncthreads();
    }
    #pragma unroll
    for (int i = 0; i < TM; i++) {
        int gm = m0 + ty * TM + i;
        #pragma unroll
        for (int j = 0; j < TN; j++) {
            int gn = n0 + tx * TN + j;
            if (gn < N) {
                float v = acc[i][j] + bias[gn];
                if (ADDC) v += Cadd[gm * ldc + gn];
                C[gm * ldc + gn] = v;
            }
        }
    }
}

// Unconditional spline on even columns -> ident (dense) + z even cols + lq
__global__ void ident_spline_kernel(const float* __restrict__ zn,
                                    const float* __restrict__ uw_u,
                                    const float* __restrict__ uh_u,
                                    const float* __restrict__ ud_u,
                                    float* __restrict__ ident,
                                    float* __restrict__ zout,
                                    float* __restrict__ lq)
{
    int idx = blockIdx.x * blockDim.x + threadIdx.x;
    if (idx >= B_ * F_) return;
    int b = idx / F_, f = idx % F_;
    float uw[8], uh[8], ud7[7];
    const float* pw = uw_u + f * 8;
    const float* ph = uh_u + f * 8;
    const float* pd = ud_u + f * 7;
    #pragma unroll
    for (int k = 0; k < 8; k++) { uw[k] = pw[k]; uh[k] = ph[k]; }
    #pragma unroll
    for (int k = 0; k < 7; k++) ud7[k] = pd[k];
    float x = zn[b * D_ + 2 * f];
    float o, l;
    rqs_inv(x, uw, uh, ud7, o, l);
    ident[b * F_ + f] = o;
    zout[b * D_ + 2 * f] = o;
    atomicAdd(&lq[b], l);
}

// Fused: p[b,f,:] = t[b,:] @ Wo[:, f*23:(f+1)*23] + bo, then conditional RQS
// inverse on trans = zn[:, 2f+1]. Block: 32 batch rows x 8 features, 128 thr,
// each thread owns 2 rows x 1 feature (23 accumulators each, padded to 24).
__global__ void __launch_bounds__(128)
wo_spline_kernel(const float* __restrict__ tmat, const float* __restrict__ Wo,
                 const float* __restrict__ bo, const float* __restrict__ zn,
                 float* __restrict__ zout, float* __restrict__ lq)
{
    constexpr int BTB = 32, BTF = 8, KC = 16;
    __shared__ float ts[BTB][129];
    __shared__ float wos[KC][BTF * 28];   // 28-stride: distinct banks per f-lane, f4-aligned
    __shared__ float bos[BTF * 24];

    int tid = threadIdx.x;
    int f_local = tid & 7;
    int b_local = tid >> 3;               // 0..15
    int b0 = blockIdx.y * BTB;
    int f0 = blockIdx.x * BTF;
    int f  = f0 + f_local;

    for (int idx = tid; idx < BTB * 128; idx += 128) {
        int r = idx >> 7, c = idx & 127;
        ts[r][c] = tmat[(b0 + r) * H_ + c];
    }
    for (int idx = tid; idx < BTF * 24; idx += 128) {
        int ff = idx / 24, oo = idx % 24;
        int col = (f0 + ff) * 23 + oo;
        bos[idx] = (oo < 23 && col < OUT_) ? bo[col] : 0.f;
    }

    float acc0[24], acc1[24];
    #pragma unroll
    for (int o = 0; o < 24; o++) { acc0[o] = 0.f; acc1[o] = 0.f; }

    for (int kc = 0; kc < H_; kc += KC) {
        __syncthreads();
        for (int idx = tid; idx < KC * BTF * 23; idx += 128) {
            int kk = idx / (BTF * 23), rem = idx % (BTF * 23);
            int ff = rem / 23, oo = rem % 23;
            int col = (f0 + ff) * 23 + oo;
            wos[kk][ff * 28 + oo] = (col < OUT_) ? Wo[(kc + kk) * OUT_ + col] : 0.f;
        }
        for (int idx = tid; idx < KC * BTF; idx += 128) {
            int kk = idx / BTF, ff = idx % BTF;
            wos[kk][ff * 28 + 23] = 0.f;  // pad slot read by the q=5 float4
        }
        __syncthreads();
        #pragma unroll
        for (int kk = 0; kk < KC; kk++) {
            float tv0 = ts[b_local][kc + kk];
            float tv1 = ts[b_local + 16][kc + kk];
            const float4* wp = reinterpret_cast<const float4*>(&wos[kk][f_local * 28]);
            #pragma unroll
            for (int q = 0; q < 6; q++) {
                float4 w4 = wp[q];
                acc0[q*4+0] += tv0 * w4.x; acc0[q*4+1] += tv0 * w4.y;
                acc0[q*4+2] += tv0 * w4.z; acc0[q*4+3] += tv0 * w4.w;
                acc1[q*4+0] += tv1 * w4.x; acc1[q*4+1] += tv1 * w4.y;
                acc1[q*4+2] += tv1 * w4.z; acc1[q*4+3] += tv1 * w4.w;
            }
        }
    }

    if (f >= F_) return;
    const float scale = 0.08838834764831845f;  // 1/sqrt(128)

    {   // row 0
        float uw[8], uh[8], ud7[7];
        #pragma unroll
        for (int o = 0; o < 8; o++) {
            uw[o] = (acc0[o]     + bos[f_local * 24 + o])     * scale;
            uh[o] = (acc0[8 + o] + bos[f_local * 24 + 8 + o]) * scale;
        }
        #pragma unroll
        for (int o = 0; o < 7; o++) ud7[o] = acc0[16 + o] + bos[f_local * 24 + 16 + o];
        int b = b0 + b_local;
        float x = zn[b * D_ + 2 * f + 1];
        float o, l;
        rqs_inv(x, uw, uh, ud7, o, l);
        zout[b * D_ + 2 * f + 1] = o;
        atomicAdd(&lq[b], l);
    }
    {   // row 1
        float uw[8], uh[8], ud7[7];
        #pragma unroll
        for (int o = 0; o < 8; o++) {
            uw[o] = (acc1[o]     + bos[f_local * 24 + o])     * scale;
            uh[o] = (acc1[8 + o] + bos[f_local * 24 + 8 + o]) * scale;
        }
        #pragma unroll
        for (int o = 0; o < 7; o++) ud7[o] = acc1[16 + o] + bos[f_local * 24 + 16 + o];
        int b = b0 + b_local + 16;
        float x = zn[b * D_ + 2 * f + 1];
        float o, l;
        rqs_inv(x, uw, uh, ud7, o, l);
        zout[b * D_ + 2 * f + 1] = o;
        atomicAdd(&lq[b], l);
    }
}

__global__ void final_kernel(const float* __restrict__ z, const float* __restrict__ loc,
                             const float* __restrict__ lsc, const float* __restrict__ lq,
                             const float* __restrict__ slog, float* __restrict__ out)
{
    int b = blockIdx.x;
    float s = 0.f;
    for (int d = threadIdx.x; d < D_; d += blockDim.x) {
        float inv = __expf(-lsc[d]);
        float u = (z[b * D_ + d] - loc[d]) * inv;
        s += lsc[d] + 0.5f * u * u;
    }
    s = block_reduce_sum(s);
    if (threadIdx.x == 0) {
        const float c = 0.5f * 550.f * 1.8378770664093453f;
        out[b] = lq[b] + slog[0] + slog[1] + slog[2] - c - s;
    }
}

// ---------------- launch ----------------
extern "C" void kernel_launch(void* const* d_in, const int* in_sizes, int n_in,
                              void* d_out, int out_size)
{
    (void)in_sizes; (void)n_in; (void)out_size;
    const float* x      = (const float*)d_in[0];
    const float* loc    = (const float*)d_in[1];
    const float* lsc    = (const float*)d_in[2];
    const float* Wi     = (const float*)d_in[3];
    const float* bi     = (const float*)d_in[4];
    const float* Wb     = (const float*)d_in[5];
    const float* bb     = (const float*)d_in[6];
    const float* Wo     = (const float*)d_in[7];
    const float* bo     = (const float*)d_in[8];
    const float* uw_u   = (const float*)d_in[9];
    const float* uh_u   = (const float*)d_in[10];
    const float* ud_u   = (const float*)d_in[11];
    const float* lower  = (const float*)d_in[12];
    const float* upper  = (const float*)d_in[13];
    const float* lu_ud  = (const float*)d_in[14];
    const float* lu_b   = (const float*)d_in[15];
    const int*   perms  = (const int*)d_in[16];
    float* outp = (float*)d_out;

    float *z, *zn, *Ap, *ident, *t, *r, *lq, *slog;
    cudaGetSymbolAddress((void**)&z,     g_z);
    cudaGetSymbolAddress((void**)&zn,    g_zn);
    cudaGetSymbolAddress((void**)&Ap,    g_Ap);
    cudaGetSymbolAddress((void**)&ident, g_id);
    cudaGetSymbolAddress((void**)&t,     g_t);
    cudaGetSymbolAddress((void**)&r,     g_r);
    cudaGetSymbolAddress((void**)&lq,    g_lq);
    cudaGetSymbolAddress((void**)&slog,  g_slog);

    zero_kernel<<<(B_ + 255) / 256, 256>>>(lq, B_);
    sumlog_kernel<<<3, 256>>>(lu_ud, slog);

    const float* src = x;
    for (int i = 2; i >= 0; i--) {
        build_A_kernel<<<dim3(3, D_), 192>>>(lower + i * D_ * D_, upper + i * D_ * D_,
                                             lu_ud + i * D_, perms + i * D_, Ap);
        // z_new = src @ Ap^T + lu_b
        gemm_k<128, 128, 8, 8, 8, true, false, false>
            <<<dim3((D_ + 127) / 128, B_ / 128), 256>>>(
                src, Ap, lu_b + i * D_, nullptr, zn, B_, D_, D_, D_, D_, D_);

        ident_spline_kernel<<<(B_ * F_ + 255) / 256, 256>>>(
            zn, uw_u + i * F_ * 8, uh_u + i * F_ * 8, ud_u + i * F_ * 7, ident, z, lq);

        // ResNet conditioner
        gemm_k<64, 64, 16, 4, 4, false, false, false>
            <<<dim3(2, B_ / 64), 256>>>(ident, Wi + i * F_ * H_, bi + i * H_, nullptr,
                                        t, B_, H_, F_, F_, H_, H_);
        gemm_k<64, 64, 16, 4, 4, false, true, false>
            <<<dim3(2, B_ / 64), 256>>>(t, Wb + (i * 4 + 0) * H_ * H_, bb + (i * 4 + 0) * H_,
                                        nullptr, r, B_, H_, H_, H_, H_, H_);
        gemm_k<64, 64, 16, 4, 4, false, true, true>
            <<<dim3(2, B_ / 64), 256>>>(r, Wb + (i * 4 + 1) * H_ * H_, bb + (i * 4 + 1) * H_,
                                        t, t, B_, H_, H_, H_, H_, H_);
        gemm_k<64, 64, 16, 4, 4, false, true, false>
            <<<dim3(2, B_ / 64), 256>>>(t, Wb + (i * 4 + 2) * H_ * H_, bb + (i * 4 + 2) * H_,
                                        nullptr, r, B_, H_, H_, H_, H_, H_);
        gemm_k<64, 64, 16, 4, 4, false, true, true>
            <<<dim3(2, B_ / 64), 256>>>(r, Wb + (i * 4 + 3) * H_ * H_, bb + (i * 4 + 3) * H_,
                                        t, t, B_, H_, H_, H_, H_, H_);

        wo_spline_kernel<<<dim3((F_ + 7) / 8, B_ / 32), 128>>>(
            t, Wo + i * H_ * OUT_, bo + i * OUT_, zn, z, lq);

        src = z;
    }

    final_kernel<<<B_, 256>>>(z, loc, lsc, lq, slog, outp);
}

// round 2
// speedup vs baseline: 1.0009x; 1.0009x over previous
#include <cuda_runtime.h>
#include <math.h>

// ---------------- problem constants ----------------
namespace {
constexpr int D_   = 550;
constexpr int LDD  = 552;    // padded row stride (float4-aligned)
constexpr int F_   = 275;
constexpr int B_   = 4096;   // N*T = 8*512
constexpr int H_   = 128;
constexpr int OUT_ = 6325;   // F_*(3*8-1)
}

// ---------------- scratch (device globals; no allocs allowed) ----------------
__device__ float g_z  [B_*LDD];   // zero-init => pad cols stay 0
__device__ float g_zn [B_*LDD];
__device__ float g_LT [LDD*LDD];
__device__ float g_UpT[LDD*LDD];
__device__ float g_ApT[LDD*LDD];
__device__ float g_id [B_*F_];
__device__ float g_t  [B_*H_];
__device__ float g_r  [B_*H_];
__device__ float g_lq [B_];
__device__ float g_slog[3];

// ---------------- helpers ----------------
__device__ __forceinline__ float softplusf(float x) {
    return (x > 20.f) ? x : log1pf(__expf(x));
}

__device__ __forceinline__ float block_reduce_sum(float v) {
    __shared__ float sred[32];
    int tid = threadIdx.x;
    #pragma unroll
    for (int o = 16; o > 0; o >>= 1) v += __shfl_down_sync(0xffffffffu, v, o);
    if ((tid & 31) == 0) sred[tid >> 5] = v;
    __syncthreads();
    if (tid < 32) {
        int nw = (blockDim.x + 31) >> 5;
        v = (tid < nw) ? sred[tid] : 0.f;
        #pragma unroll
        for (int o = 16; o > 0; o >>= 1) v += __shfl_down_sync(0xffffffffu, v, o);
    }
    return v;  // valid in thread 0
}

// Inverse monotonic RQS with linear tails (nflows math). All register-resident.
__device__ __forceinline__ void rqs_inv(float x, const float* uw, const float* uh,
                                        const float* ud7, float& out, float& ld)
{
    const float TB = 3.f;
    bool inside = (x >= -TB) && (x <= TB);
    float xi = fminf(fmaxf(x, -TB), TB);

    float cw[9], ch[9], dd[9];
    {
        float m = uw[0];
        #pragma unroll
        for (int k = 1; k < 8; k++) m = fmaxf(m, uw[k]);
        float e[8]; float s = 0.f;
        #pragma unroll
        for (int k = 0; k < 8; k++) { e[k] = __expf(uw[k] - m); s += e[k]; }
        float inv = 1.f / s;
        float cum = 0.f;
        cw[0] = -TB;
        #pragma unroll
        for (int k = 0; k < 7; k++) { cum += 0.001f + 0.992f * e[k] * inv; cw[k+1] = 6.f * cum - 3.f; }
        cw[8] = TB;
    }
    {
        float m = uh[0];
        #pragma unroll
        for (int k = 1; k < 8; k++) m = fmaxf(m, uh[k]);
        float e[8]; float s = 0.f;
        #pragma unroll
        for (int k = 0; k < 8; k++) { e[k] = __expf(uh[k] - m); s += e[k]; }
        float inv = 1.f / s;
        float cum = 0.f;
        ch[0] = -TB;
        #pragma unroll
        for (int k = 0; k < 7; k++) { cum += 0.001f + 0.992f * e[k] * inv; ch[k+1] = 6.f * cum - 3.f; }
        ch[8] = TB;
    }
    const float DCONSTF = 0.53974175f;  // log(exp(0.999)-1)
    float dend = 0.001f + log1pf(__expf(DCONSTF));
    dd[0] = dend; dd[8] = dend;
    #pragma unroll
    for (int k = 0; k < 7; k++) dd[k+1] = 0.001f + softplusf(ud7[k]);

    int cnt = 0;
    #pragma unroll
    for (int k = 0; k < 9; k++) {
        float lo = ch[k] + (k == 8 ? 1e-6f : 0.f);
        cnt += (xi >= lo) ? 1 : 0;
    }
    int idx = cnt - 1; idx = idx < 0 ? 0 : (idx > 7 ? 7 : idx);

    float icw = 0.f, iw = 1.f, ich = 0.f, ih = 1.f, d0 = 1.f, d1 = 1.f;
    #pragma unroll
    for (int k = 0; k < 8; k++) {
        if (k == idx) {
            icw = cw[k]; iw = cw[k+1] - cw[k];
            ich = ch[k]; ih = ch[k+1] - ch[k];
            d0 = dd[k]; d1 = dd[k+1];
        }
    }

    float delta = ih / iw;
    float t  = xi - ich;
    float s2 = d0 + d1 - 2.f * delta;
    float aa = t * s2 + ih * (delta - d0);
    float bb = ih * d0 - t * s2;
    float cc = -delta * t;
    float disc = bb * bb - 4.f * aa * cc;
    float root = (2.f * cc) / (-bb - sqrtf(disc));
    float o = root * iw + icw;
    float tm = root * (1.f - root);
    float den = delta + s2 * tm;
    float omr = 1.f - root;
    float dnum = delta * delta * (d1 * root * root + 2.f * delta * tm + d0 * omr * omr);
    float l = 2.f * __logf(den) - __logf(dnum);

    out = inside ? o : x;
    ld  = inside ? l : 0.f;
}

// ---------------- small kernels ----------------
__global__ void zero_kernel(float* p, int n) {
    int i = blockIdx.x * blockDim.x + threadIdx.x;
    if (i < n) p[i] = 0.f;
}

__global__ void copy_pad_kernel(const float* __restrict__ x, float* __restrict__ z) {
    int i = blockIdx.x * blockDim.x + threadIdx.x;
    if (i >= B_ * D_) return;
    int b = i / D_, d = i % D_;
    z[b * LDD + d] = x[i];
}

__global__ void sumlog_kernel(const float* __restrict__ lu_ud, float* __restrict__ out) {
    int i = blockIdx.x;  // layer
    float s = 0.f;
    for (int d = threadIdx.x; d < D_; d += blockDim.x)
        s += __logf(softplusf(lu_ud[i * D_ + d]) + 0.001f);
    s = block_reduce_sum(s);
    if (threadIdx.x == 0) out[i] = s;
}

// Materialize LT[m,d] = L[d,m] (unit diag) and UpT[perm[k], m] = Udense[m,k].
// blockIdx.y = row index (m for LT, k for UpT); blockIdx.z selects which.
__global__ void build_lt_upt_kernel(const float* __restrict__ lower,
                                    const float* __restrict__ upper,
                                    const float* __restrict__ lu_ud,
                                    const int* __restrict__ perm,
                                    float* __restrict__ LT, float* __restrict__ UpT)
{
    int c = blockIdx.x * blockDim.x + threadIdx.x;
    int rr = blockIdx.y;
    if (c >= D_) return;
    if (blockIdx.z == 0) {
        // LT[m=rr, d=c]
        int m = rr, d = c;
        float v = (m < d) ? lower[d * D_ + m] : ((m == d) ? 1.f : 0.f);
        LT[m * LDD + d] = v;
    } else {
        // UpT[perm[k=rr], m=c]
        int k = rr, m = c;
        float v;
        if (m < k)       v = upper[m * D_ + k];
        else if (m == k) v = softplusf(lu_ud[k]) + 0.001f;
        else             v = 0.f;
        UpT[perm[k] * LDD + m] = v;
    }
}

// ---------------- fast SGEMM: C = A @ B + bias ----------------
// A: [M x lda] row-major (contraction contiguous); B: [K x ldb] row-major
// (output-dim contiguous). BK = 16 fixed, 256 threads.
template<int BM, int BN, int TM, int TN, bool HASB>
__global__ void __launch_bounds__(256)
sgemm_tn(const float* __restrict__ A, const float* __restrict__ Bm,
         const float* __restrict__ bias, float* __restrict__ C,
         int M, int N, int K, int lda, int ldb, int ldc)
{
    constexpr int BK = 16;
    constexpr int TX = BN / TN, TY = BM / TM;
    static_assert(TX * TY == 256, "thread tiling");
    __shared__ __align__(16) float As[BK][BM];
    __shared__ __align__(16) float Bs[BK][BN];
    int tid = threadIdx.x;
    int tx = tid % TX, ty = tid / TX;
    int m0 = blockIdx.y * BM, n0 = blockIdx.x * BN;

    float acc[TM][TN];
    #pragma unroll
    for (int i = 0; i < TM; i++)
        #pragma unroll
        for (int j = 0; j < TN; j++) acc[i][j] = 0.f;

    for (int k0 = 0; k0 < K; k0 += BK) {
        // A tile: BM x 16, float4 along k, transposed store
        #pragma unroll
        for (int idx = tid; idx < BM * 4; idx += 256) {
            int m = idx >> 2, k4 = (idx & 3) << 2;
            int gm = m0 + m, gk = k0 + k4;
            float4 v = make_float4(0.f, 0.f, 0.f, 0.f);
            if (gm < M && gk < K)
                v = *reinterpret_cast<const float4*>(&A[gm * lda + gk]);
            As[k4 + 0][m] = v.x; As[k4 + 1][m] = v.y;
            As[k4 + 2][m] = v.z; As[k4 + 3][m] = v.w;
        }
        // B tile: 16 x BN, float4 along n, direct store
        #pragma unroll
        for (int idx = tid; idx < BN * 4; idx += 256) {
            int k = idx / (BN / 4), n4 = (idx % (BN / 4)) << 2;
            int gk = k0 + k, gn = n0 + n4;
            float4 v = make_float4(0.f, 0.f, 0.f, 0.f);
            if (gk < K && gn < N)
                v = *reinterpret_cast<const float4*>(&Bm[gk * ldb + gn]);
            *reinterpret_cast<float4*>(&Bs[k][n4]) = v;
        }
        __syncthreads();
        #pragma unroll
        for (int kk = 0; kk < BK; kk++) {
            float a[TM], b[TN];
            #pragma unroll
            for (int i = 0; i < TM / 4; i++)
                *reinterpret_cast<float4*>(&a[4 * i]) =
                    *reinterpret_cast<const float4*>(&As[kk][ty * TM + 4 * i]);
            #pragma unroll
            for (int j = 0; j < TN / 4; j++)
                *reinterpret_cast<float4*>(&b[4 * j]) =
                    *reinterpret_cast<const float4*>(&Bs[kk][tx * TN + 4 * j]);
            #pragma unroll
            for (int i = 0; i < TM; i++)
                #pragma unroll
                for (int j = 0; j < TN; j++)
                    acc[i][j] = fmaf(a[i], b[j], acc[i][j]);
        }
        __syncthreads();
    }
    #pragma unroll
    for (int i = 0; i < TM; i++) {
        int gm = m0 + ty * TM + i;
        if (gm < M) {
            #pragma unroll
            for (int j = 0; j < TN; j++) {
                int gn = n0 + tx * TN + j;
                if (gn < N)
                    C[gm * ldc + gn] = acc[i][j] + (HASB ? bias[gn] : 0.f);
            }
        }
    }
}

// ---------------- legacy small GEMM (resnet) ----------------
template<int BM, int BN, int BK, int TM, int TN, bool RELUA, bool ADDC>
__global__ void __launch_bounds__((BM/TM)*(BN/TN))
gemm_k(const float* __restrict__ A, const float* __restrict__ B,
       const float* __restrict__ bias, const float* __restrict__ Cadd,
       float* __restrict__ C, int M, int N, int K, int lda, int ldb, int ldc)
{
    constexpr int TX = BN / TN, TY = BM / TM, NT = TX * TY;
    __shared__ float As[BK][BM];
    __shared__ float Bs[BK][BN];
    int tid = threadIdx.x;
    int tx = tid % TX, ty = tid / TX;
    int m0 = blockIdx.y * BM, n0 = blockIdx.x * BN;
    float acc[TM][TN];
    #pragma unroll
    for (int i = 0; i < TM; i++)
        #pragma unroll
        for (int j = 0; j < TN; j++) acc[i][j] = 0.f;

    for (int k0 = 0; k0 < K; k0 += BK) {
        #pragma unroll
        for (int idx = tid; idx < BM * BK; idx += NT) {
            int r = idx / BK, c = idx % BK;
            int gm = m0 + r, gk = k0 + c;
            float v = (gk < K) ? A[gm * lda + gk] : 0.f;
            if (RELUA) v = fmaxf(v, 0.f);
            As[c][r] = v;
        }
        #pragma unroll
        for (int idx = tid; idx < BK * BN; idx += NT) {
            int r = idx / BN, c = idx % BN;
            int gk = k0 + r, gn = n0 + c;
            Bs[r][c] = (gk < K && gn < N) ? B[gk * ldb + gn] : 0.f;
        }
        __syncthreads();
        #pragma unroll
        for (int kk = 0; kk < BK; kk++) {
            float ra[TM], rb[TN];
            #pragma unroll
            for (int i = 0; i < TM; i++) ra[i] = As[kk][ty * TM + i];
            #pragma unroll
            for (int j = 0; j < TN; j++) rb[j] = Bs[kk][tx * TN + j];
            #pragma unroll
            for (int i = 0; i < TM; i++)
                #pragma unroll
                for (int j = 0; j < TN; j++)
                    acc[i][j] += ra[i] * rb[j];
        }
        __syncthreads();
    }
    #pragma unroll
    for (int i = 0; i < TM; i++) {
        int gm = m0 + ty * TM + i;
        #pragma unroll
        for (int j = 0; j < TN; j++) {
            int gn = n0 + tx * TN + j;
            if (gn < N) {
                float v = acc[i][j] + bias[gn];
                if (ADDC) v += Cadd[gm * ldc + gn];
                C[gm * ldc + gn] = v;
            }
        }
    }
}

// Unconditional spline on even columns -> ident (dense) + z even cols + lq
__global__ void ident_spline_kernel(const float* __restrict__ zn,
                                    const float* __restrict__ uw_u,
                                    const float* __restrict__ uh_u,
                                    const float* __restrict__ ud_u,
                                    float* __restrict__ ident,
                                    float* __restrict__ zout,
                                    float* __restrict__ lq)
{
    int idx = blockIdx.x * blockDim.x + threadIdx.x;
    if (idx >= B_ * F_) return;
    int b = idx / F_, f = idx % F_;
    float uw[8], uh[8], ud7[7];
    const float* pw = uw_u + f * 8;
    const float* ph = uh_u + f * 8;
    const float* pd = ud_u + f * 7;
    #pragma unroll
    for (int k = 0; k < 8; k++) { uw[k] = pw[k]; uh[k] = ph[k]; }
    #pragma unroll
    for (int k = 0; k < 7; k++) ud7[k] = pd[k];
    float x = zn[b * LDD + 2 * f];
    float o, l;
    rqs_inv(x, uw, uh, ud7, o, l);
    ident[b * F_ + f] = o;
    zout[b * LDD + 2 * f] = o;
    atomicAdd(&lq[b], l);
}

// Fused: p[b,f,:] = t[b,:] @ Wo[:, f*23:(f+1)*23] + bo, then conditional RQS
// inverse on trans = zn[:, 2f+1].
__global__ void __launch_bounds__(128)
wo_spline_kernel(const float* __restrict__ tmat, const float* __restrict__ Wo,
                 const float* __restrict__ bo, const float* __restrict__ zn,
                 float* __restrict__ zout, float* __restrict__ lq)
{
    constexpr int BTB = 32, BTF = 8, KC = 16;
    __shared__ float ts[BTB][129];
    __shared__ float wos[KC][BTF * 28];
    __shared__ float bos[BTF * 24];

    int tid = threadIdx.x;
    int f_local = tid & 7;
    int b_local = tid >> 3;               // 0..15
    int b0 = blockIdx.y * BTB;
    int f0 = blockIdx.x * BTF;
    int f  = f0 + f_local;

    for (int idx = tid; idx < BTB * 128; idx += 128) {
        int r = idx >> 7, c = idx & 127;
        ts[r][c] = tmat[(b0 + r) * H_ + c];
    }
    for (int idx = tid; idx < BTF * 24; idx += 128) {
        int ff = idx / 24, oo = idx % 24;
        int col = (f0 + ff) * 23 + oo;
        bos[idx] = (oo < 23 && col < OUT_) ? bo[col] : 0.f;
    }

    float acc0[24], acc1[24];
    #pragma unroll
    for (int o = 0; o < 24; o++) { acc0[o] = 0.f; acc1[o] = 0.f; }

    for (int kc = 0; kc < H_; kc += KC) {
        __syncthreads();
        for (int idx = tid; idx < KC * BTF * 23; idx += 128) {
            int kk = idx / (BTF * 23), rem = idx % (BTF * 23);
            int ff = rem / 23, oo = rem % 23;
            int col = (f0 + ff) * 23 + oo;
            wos[kk][ff * 28 + oo] = (col < OUT_) ? Wo[(kc + kk) * OUT_ + col] : 0.f;
        }
        for (int idx = tid; idx < KC * BTF; idx += 128) {
            int kk = idx / BTF, ff = idx % BTF;
            wos[kk][ff * 28 + 23] = 0.f;
        }
        __syncthreads();
        #pragma unroll
        for (int kk = 0; kk < KC; kk++) {
            float tv0 = ts[b_local][kc + kk];
            float tv1 = ts[b_local + 16][kc + kk];
            const float4* wp = reinterpret_cast<const float4*>(&wos[kk][f_local * 28]);
            #pragma unroll
            for (int q = 0; q < 6; q++) {
                float4 w4 = wp[q];
                acc0[q*4+0] += tv0 * w4.x; acc0[q*4+1] += tv0 * w4.y;
                acc0[q*4+2] += tv0 * w4.z; acc0[q*4+3] += tv0 * w4.w;
                acc1[q*4+0] += tv1 * w4.x; acc1[q*4+1] += tv1 * w4.y;
                acc1[q*4+2] += tv1 * w4.z; acc1[q*4+3] += tv1 * w4.w;
            }
        }
    }

    if (f >= F_) return;
    const float scale = 0.08838834764831845f;  // 1/sqrt(128)

    {   // row 0
        float uw[8], uh[8], ud7[7];
        #pragma unroll
        for (int o = 0; o < 8; o++) {
            uw[o] = (acc0[o]     + bos[f_local * 24 + o])     * scale;
            uh[o] = (acc0[8 + o] + bos[f_local * 24 + 8 + o]) * scale;
        }
        #pragma unroll
        for (int o = 0; o < 7; o++) ud7[o] = acc0[16 + o] + bos[f_local * 24 + 16 + o];
        int b = b0 + b_local;
        float x = zn[b * LDD + 2 * f + 1];
        float o, l;
        rqs_inv(x, uw, uh, ud7, o, l);
        zout[b * LDD + 2 * f + 1] = o;
        atomicAdd(&lq[b], l);
    }
    {   // row 1
        float uw[8], uh[8], ud7[7];
        #pragma unroll
        for (int o = 0; o < 8; o++) {
            uw[o] = (acc1[o]     + bos[f_local * 24 + o])     * scale;
            uh[o] = (acc1[8 + o] + bos[f_local * 24 + 8 + o]) * scale;
        }
        #pragma unroll
        for (int o = 0; o < 7; o++) ud7[o] = acc1[16 + o] + bos[f_local * 24 + 16 + o];
        int b = b0 + b_local + 16;
        float x = zn[b * LDD + 2 * f + 1];
        float o, l;
        rqs_inv(x, uw, uh, ud7, o, l);
        zout[b * LDD + 2 * f + 1] = o;
        atomicAdd(&lq[b], l);
    }
}

__global__ void final_kernel(const float* __restrict__ z, const float* __restrict__ loc,
                             const float* __restrict__ lsc, const float* __restrict__ lq,
                             const float* __restrict__ slog, float* __restrict__ out)
{
    int b = blockIdx.x;
    float s = 0.f;
    for (int d = threadIdx.x; d < D_; d += blockDim.x) {
        float inv = __expf(-lsc[d]);
        float u = (z[b * LDD + d] - loc[d]) * inv;
        s += lsc[d] + 0.5f * u * u;
    }
    s = block_reduce_sum(s);
    if (threadIdx.x == 0) {
        const float c = 0.5f * 550.f * 1.8378770664093453f;
        out[b] = lq[b] + slog[0] + slog[1] + slog[2] - c - s;
    }
}

// ---------------- launch ----------------
extern "C" void kernel_launch(void* const* d_in, const int* in_sizes, int n_in,
                              void* d_out, int out_size)
{
    (void)in_sizes; (void)n_in; (void)out_size;
    const float* x      = (const float*)d_in[0];
    const float* loc    = (const float*)d_in[1];
    const float* lsc    = (const float*)d_in[2];
    const float* Wi     = (const float*)d_in[3];
    const float* bi     = (const float*)d_in[4];
    const float* Wb     = (const float*)d_in[5];
    const float* bb     = (const float*)d_in[6];
    const float* Wo     = (const float*)d_in[7];
    const float* bo     = (const float*)d_in[8];
    const float* uw_u   = (const float*)d_in[9];
    const float* uh_u   = (const float*)d_in[10];
    const float* ud_u   = (const float*)d_in[11];
    const float* lower  = (const float*)d_in[12];
    const float* upper  = (const float*)d_in[13];
    const float* lu_ud  = (const float*)d_in[14];
    const float* lu_b   = (const float*)d_in[15];
    const int*   perms  = (const int*)d_in[16];
    float* outp = (float*)d_out;

    float *z, *zn, *LT, *UpT, *ApT, *ident, *t, *r, *lq, *slog;
    cudaGetSymbolAddress((void**)&z,     g_z);
    cudaGetSymbolAddress((void**)&zn,    g_zn);
    cudaGetSymbolAddress((void**)&LT,    g_LT);
    cudaGetSymbolAddress((void**)&UpT,   g_UpT);
    cudaGetSymbolAddress((void**)&ApT,   g_ApT);
    cudaGetSymbolAddress((void**)&ident, g_id);
    cudaGetSymbolAddress((void**)&t,     g_t);
    cudaGetSymbolAddress((void**)&r,     g_r);
    cudaGetSymbolAddress((void**)&lq,    g_lq);
    cudaGetSymbolAddress((void**)&slog,  g_slog);

    zero_kernel<<<(B_ + 255) / 256, 256>>>(lq, B_);
    sumlog_kernel<<<3, 256>>>(lu_ud, slog);
    copy_pad_kernel<<<(B_ * D_ + 255) / 256, 256>>>(x, z);

    for (int i = 2; i >= 0; i--) {
        // Materialize LT / UpT, then ApT = UpT @ LT (dense SGEMM)
        build_lt_upt_kernel<<<dim3((D_ + 255) / 256, D_, 2), 256>>>(
            lower + i * D_ * D_, upper + i * D_ * D_,
            lu_ud + i * D_, perms + i * D_, LT, UpT);
        sgemm_tn<64, 64, 4, 4, false>
            <<<dim3((D_ + 63) / 64, (D_ + 63) / 64), 256>>>(
                UpT, LT, nullptr, ApT, D_, D_, D_, LDD, LDD, LDD);

        // zn = z @ ApT + lu_b   (C[b,d] = sum_j z[b,j] * ApT[j,d])
        sgemm_tn<128, 128, 8, 8, true>
            <<<dim3((D_ + 127) / 128, B_ / 128), 256>>>(
                z, ApT, lu_b + i * D_, zn, B_, D_, D_, LDD, LDD, LDD);

        ident_spline_kernel<<<(B_ * F_ + 255) / 256, 256>>>(
            zn, uw_u + i * F_ * 8, uh_u + i * F_ * 8, ud_u + i * F_ * 7, ident, z, lq);

        // ResNet conditioner
        gemm_k<64, 64, 16, 4, 4, false, false>
            <<<dim3(2, B_ / 64), 256>>>(ident, Wi + i * F_ * H_, bi + i * H_, nullptr,
                                        t, B_, H_, F_, F_, H_, H_);
        gemm_k<64, 64, 16, 4, 4, true, false>
            <<<dim3(2, B_ / 64), 256>>>(t, Wb + (i * 4 + 0) * H_ * H_, bb + (i * 4 + 0) * H_,
                                        nullptr, r, B_, H_, H_, H_, H_, H_);
        gemm_k<64, 64, 16, 4, 4, true, true>
            <<<dim3(2, B_ / 64), 256>>>(r, Wb + (i * 4 + 1) * H_ * H_, bb + (i * 4 + 1) * H_,
                                        t, t, B_, H_, H_, H_, H_, H_);
        gemm_k<64, 64, 16, 4, 4, true, false>
            <<<dim3(2, B_ / 64), 256>>>(t, Wb + (i * 4 + 2) * H_ * H_, bb + (i * 4 + 2) * H_,
                                        nullptr, r, B_, H_, H_, H_, H_, H_);
        gemm_k<64, 64, 16, 4, 4, true, true>
            <<<dim3(2, B_ / 64), 256>>>(r, Wb + (i * 4 + 3) * H_ * H_, bb + (i * 4 + 3) * H_,
                                        t, t, B_, H_, H_, H_, H_, H_);

        wo_spline_kernel<<<dim3((F_ + 7) / 8, B_ / 32), 128>>>(
            t, Wo + i * H_ * OUT_, bo + i * OUT_, zn, z, lq);
    }

    final_kernel<<<B_, 256>>>(z, loc, lsc, lq, slog, outp);
}